// round 4
// baseline (speedup 1.0000x reference)
#include <cuda_runtime.h>

// AssociatorLoss: B=32, N=32
//   one[b,i,j,k,l] = sum_m a[b,i,m,l] * a[b,j,k,m]
//   two[b,i,j,k,l] = sum_m a[b,m,k,l] * a[b,i,j,m]
//   KL = sum two * log(two/one) / B
//
// R3 redesign: evidence from R0(288us, 384 LDS/thr) vs R2-shape(358us,
// 512 LDS/thr) says we are LDS/issue bound, not spill bound. New shape:
// 256 thr/CTA, 8j x 8l per-thread tile (2 l-phases) -> 4 FMA per loaded
// float (was 2.67); k-strided loads amortized over 8 of the other index.
// Reduction fused into the main kernel (last-CTA pattern) so the launch
// stream is period-1 (ncu -s 5 finally captures the MAIN kernel) and the
// ~5us reduce launch leaves the timed path.

__device__ float g_partial[1024];
__device__ int   g_count = 0;

// Accurate natural log: reduce to z in [sqrt(2)/2, sqrt(2)), atanh series.
// |abs err| ~1e-7; keeps the 33M-term KL sum far inside the 1e-3 tolerance.
__device__ __forceinline__ float acc_logf(float x) {
    int ix = __float_as_int(x);
    int t  = ix - 0x3f3504f3;
    int e  = t >> 23;
    float z = __int_as_float(ix - (t & 0xff800000));
    float f = z - 1.0f;
    float s = __fdividef(f, 2.0f + f);
    float s2 = s * s;
    float p = fmaf(s2, fmaf(s2, fmaf(s2, 0.28571429f, 0.4f), 0.66666667f), 2.0f);
    return fmaf((float)e, 0.69314718f, s * p);
}

__global__ __launch_bounds__(256, 1)
void assoc_kernel(const float* __restrict__ A, float* __restrict__ out) {
    extern __shared__ float4 sc[];        // 8192 float4 = 128 KB, swizzled cube

    const int i = blockIdx.x;             // 0..31
    const int b = blockIdx.y;             // 0..31
    const int tid = threadIdx.x;
    const float4* ab4 = reinterpret_cast<const float4*>(A + b * 32768);

    // ---- stage a[b] into SMEM, swizzled: chunk c of row r -> c ^ (r & 7) ----
    #pragma unroll 8
    for (int it = 0; it < 32; ++it) {
        int g = it * 256 + tid;                       // coalesced float4 index
        float4 v = ab4[g];
        int pos = (g & ~7) | ((g ^ (g >> 3)) & 7);    // row*8 + (c ^ (row&7))
        sc[pos] = v;
    }
    __syncthreads();

    const float* scf = reinterpret_cast<const float*>(sc);
    const int k  = tid & 31;         // lane = k
    const int w  = tid >> 5;         // warp 0..7
    const int jg = w >> 1;           // 4 j-groups of 8
    const int lh = w & 1;            // l-half: chunks lh*4 .. lh*4+3
    const int jb = jg * 8;
    const int ks = k & 7;

    float kl = 0.0f;

    #pragma unroll
    for (int ph = 0; ph < 2; ++ph) {
        const int c0 = lh * 4 + ph * 2;       // two l-chunks => 8 l values
        const int c1 = c0 + 1;

        float acc1[8][8], acc2[8][8];
        #pragma unroll
        for (int jj = 0; jj < 8; ++jj)
            #pragma unroll
            for (int q = 0; q < 8; ++q) { acc1[jj][q] = 0.0f; acc2[jj][q] = 0.0f; }

        #pragma unroll
        for (int mc = 0; mc < 8; ++mc) {      // m = mc*4 + mm
            // rm4[jj] = a[b, jb+jj, k, mc*4 .. +3]  (k-strided, swizzled)
            float4 rm4[8];
            #pragma unroll
            for (int jj = 0; jj < 8; ++jj)
                rm4[jj] = sc[((jb + jj) * 32 + k) * 8 + (mc ^ ks)];

            #pragma unroll
            for (int mm = 0; mm < 4; ++mm) {
                const int m  = mc * 4 + mm;
                const int ms = m & 7;
                // broadcast rows of slab i
                float4 s0 = sc[(i * 32 + m) * 8 + (c0 ^ ms)];   // a[b,i,m,l]
                float4 s1 = sc[(i * 32 + m) * 8 + (c1 ^ ms)];
                // k-strided rows of slab m
                float4 v0 = sc[(m * 32 + k) * 8 + (c0 ^ ks)];   // a[b,m,k,l]
                float4 v1 = sc[(m * 32 + k) * 8 + (c1 ^ ks)];

                #pragma unroll
                for (int jj = 0; jj < 8; ++jj) {
                    const int j = jb + jj;
                    // scalar broadcast: a[b,i,j,m]
                    float aj = scf[((((i * 32 + j) * 8) + (mc ^ (j & 7))) << 2) | mm];
                    float rv = ((const float*)&rm4[jj])[mm];
                    acc2[jj][0] = fmaf(aj, v0.x, acc2[jj][0]);
                    acc2[jj][1] = fmaf(aj, v0.y, acc2[jj][1]);
                    acc2[jj][2] = fmaf(aj, v0.z, acc2[jj][2]);
                    acc2[jj][3] = fmaf(aj, v0.w, acc2[jj][3]);
                    acc2[jj][4] = fmaf(aj, v1.x, acc2[jj][4]);
                    acc2[jj][5] = fmaf(aj, v1.y, acc2[jj][5]);
                    acc2[jj][6] = fmaf(aj, v1.z, acc2[jj][6]);
                    acc2[jj][7] = fmaf(aj, v1.w, acc2[jj][7]);
                    acc1[jj][0] = fmaf(rv, s0.x, acc1[jj][0]);
                    acc1[jj][1] = fmaf(rv, s0.y, acc1[jj][1]);
                    acc1[jj][2] = fmaf(rv, s0.z, acc1[jj][2]);
                    acc1[jj][3] = fmaf(rv, s0.w, acc1[jj][3]);
                    acc1[jj][4] = fmaf(rv, s1.x, acc1[jj][4]);
                    acc1[jj][5] = fmaf(rv, s1.y, acc1[jj][5]);
                    acc1[jj][6] = fmaf(rv, s1.z, acc1[jj][6]);
                    acc1[jj][7] = fmaf(rv, s1.w, acc1[jj][7]);
                }
            }
        }

        // ---- KL for this 8x8 tile: two * log(two/one) ----
        #pragma unroll
        for (int jj = 0; jj < 8; ++jj)
            #pragma unroll
            for (int q = 0; q < 8; ++q) {
                float two = acc2[jj][q];
                float one = acc1[jj][q];
                kl = fmaf(two, acc_logf(__fdividef(two, one)), kl);
            }
    }

    // ---- deterministic block reduction ----
    #pragma unroll
    for (int o = 16; o > 0; o >>= 1)
        kl += __shfl_xor_sync(0xffffffffu, kl, o);

    __shared__ float sred[8];
    __shared__ bool  s_last;
    if ((tid & 31) == 0) sred[w] = kl;
    __syncthreads();

    if (tid == 0) {
        float s = 0.0f;
        #pragma unroll
        for (int x = 0; x < 8; ++x) s += sred[x];
        g_partial[b * 32 + i] = s;
        __threadfence();
        s_last = (atomicAdd(&g_count, 1) == 1023);
    }
    __syncthreads();

    // ---- last CTA: deterministic double-precision final reduce ----
    if (s_last && tid < 32) {
        __threadfence();
        double s = 0.0;
        #pragma unroll
        for (int it = 0; it < 32; ++it)
            s += (double)g_partial[it * 32 + tid];
        #pragma unroll
        for (int o = 16; o > 0; o >>= 1)
            s += __shfl_xor_sync(0xffffffffu, s, o);
        if (tid == 0) {
            out[0] = (float)(s * (1.0 / 32.0));   // / B
            g_count = 0;                          // reset for next graph replay
        }
    }
}

extern "C" void kernel_launch(void* const* d_in, const int* in_sizes, int n_in,
                              void* d_out, int out_size) {
    const float* A = (const float*)d_in[0];
    float* out = (float*)d_out;

    cudaFuncSetAttribute(assoc_kernel,
                         cudaFuncAttributeMaxDynamicSharedMemorySize, 131072);

    dim3 grid(32, 32);   // (i, b)
    assoc_kernel<<<grid, 256, 131072>>>(A, out);
}

// round 5
// speedup vs baseline: 2.0199x; 2.0199x over previous
#include <cuda_runtime.h>

// AssociatorLoss: B=32, N=32
//   one[b,i,j,k,l] = sum_m a[b,i,m,l] * a[b,j,k,m]
//   two[b,i,j,k,l] = sum_m a[b,m,k,l] * a[b,i,j,m]
//   KL = sum two * log(two/one) / B
//
// R5: R0's 512-thr 4jx8l shape (best measured) with the two taxes removed:
//  - spills: scalar aj + tight live set ~115 regs (cap 128) -> none
//  - hot-loop ALU: slab i staged UNSWIZZLED (4KB) so all broadcast loads are
//    [base+imm]; swizzled-cube loads use per-mc precomputed base registers.
// Reduction stays fused (last-CTA) so ncu -s5 captures the main kernel.

__device__ float g_partial[1024];
__device__ int   g_count = 0;

// Accurate natural log: reduce to z in [sqrt(2)/2, sqrt(2)), atanh series.
// |abs err| ~1e-7; keeps the 33M-term KL sum far inside the 1e-3 tolerance.
__device__ __forceinline__ float acc_logf(float x) {
    int ix = __float_as_int(x);
    int t  = ix - 0x3f3504f3;
    int e  = t >> 23;
    float z = __int_as_float(ix - (t & 0xff800000));
    float f = z - 1.0f;
    float s = __fdividef(f, 2.0f + f);
    float s2 = s * s;
    float p = fmaf(s2, fmaf(s2, fmaf(s2, 0.28571429f, 0.4f), 0.66666667f), 2.0f);
    return fmaf((float)e, 0.69314718f, s * p);
}

__global__ __launch_bounds__(512, 1)
void assoc_kernel(const float* __restrict__ A, float* __restrict__ out) {
    extern __shared__ float4 sc4[];            // [0,8192): swizzled cube (128KB)
    float*        scf = reinterpret_cast<float*>(sc4);
    float*        sif = scf + 32768;           // [32768,33792): slab i, unswizzled
    const float4* si4 = reinterpret_cast<const float4*>(sif);

    const int i = blockIdx.x;                  // 0..31
    const int b = blockIdx.y;                  // 0..31
    const int tid = threadIdx.x;
    const float4* ab4 = reinterpret_cast<const float4*>(A + b * 32768);

    // ---- stage swizzled cube: chunk c of row r -> c ^ (r & 7) ----
    #pragma unroll
    for (int it = 0; it < 16; ++it) {
        int g = it * 512 + tid;
        float4 v = ab4[g];
        int pos = (g & ~7) | ((g ^ (g >> 3)) & 7);
        sc4[pos] = v;
    }
    // ---- stage unswizzled slab i (a[b,i,:,:], 1024 floats) ----
    sif[tid]       = A[b * 32768 + i * 1024 + tid];
    sif[tid + 512] = A[b * 32768 + i * 1024 + 512 + tid];
    __syncthreads();

    const int k  = tid & 31;        // lane = k
    const int w  = tid >> 5;        // warp 0..15
    const int jg = w & 7;           // 8 j-groups of 4
    const int lh = w >> 3;          // l-half (0/1)
    const int jb = jg * 4;
    const int ks = k & 7;
    const int k8 = k * 8;

    float kl = 0.0f;

    #pragma unroll
    for (int ph = 0; ph < 2; ++ph) {
        const int c0 = lh * 4 + ph * 2;        // two l-chunks => 8 l values
        const int c1 = c0 + 1;
        const int vb0 = k8 + (c0 ^ ks);        // float4-idx base for v0 (m=0)
        const int vb1 = k8 + (c1 ^ ks);

        float acc1[4][8], acc2[4][8];
        #pragma unroll
        for (int jj = 0; jj < 4; ++jj)
            #pragma unroll
            for (int q = 0; q < 8; ++q) { acc1[jj][q] = 0.0f; acc2[jj][q] = 0.0f; }

        #pragma unroll
        for (int mc = 0; mc < 8; ++mc) {       // m = mc*4 + mm
            const int rb = jb * 256 + k8 + (mc ^ ks);
            float4 rm4[4];                     // a[b, jb+jj, k, mc*4..+3]
            #pragma unroll
            for (int jj = 0; jj < 4; ++jj)
                rm4[jj] = sc4[rb + jj * 256];

            #pragma unroll
            for (int mm = 0; mm < 4; ++mm) {
                const int m = mc * 4 + mm;
                float4 s0 = si4[m * 8 + c0];           // a[b,i,m,l]  broadcast
                float4 s1 = si4[m * 8 + c1];
                float4 v0 = sc4[vb0 + m * 256];        // a[b,m,k,l]  strided
                float4 v1 = sc4[vb1 + m * 256];

                #pragma unroll
                for (int jj = 0; jj < 4; ++jj) {
                    float aj = sif[(jb + jj) * 32 + m];   // a[b,i,j,m] broadcast
                    float rv = ((const float*)&rm4[jj])[mm];
                    acc2[jj][0] = fmaf(aj, v0.x, acc2[jj][0]);
                    acc2[jj][1] = fmaf(aj, v0.y, acc2[jj][1]);
                    acc2[jj][2] = fmaf(aj, v0.z, acc2[jj][2]);
                    acc2[jj][3] = fmaf(aj, v0.w, acc2[jj][3]);
                    acc2[jj][4] = fmaf(aj, v1.x, acc2[jj][4]);
                    acc2[jj][5] = fmaf(aj, v1.y, acc2[jj][5]);
                    acc2[jj][6] = fmaf(aj, v1.z, acc2[jj][6]);
                    acc2[jj][7] = fmaf(aj, v1.w, acc2[jj][7]);
                    acc1[jj][0] = fmaf(rv, s0.x, acc1[jj][0]);
                    acc1[jj][1] = fmaf(rv, s0.y, acc1[jj][1]);
                    acc1[jj][2] = fmaf(rv, s0.z, acc1[jj][2]);
                    acc1[jj][3] = fmaf(rv, s0.w, acc1[jj][3]);
                    acc1[jj][4] = fmaf(rv, s1.x, acc1[jj][4]);
                    acc1[jj][5] = fmaf(rv, s1.y, acc1[jj][5]);
                    acc1[jj][6] = fmaf(rv, s1.z, acc1[jj][6]);
                    acc1[jj][7] = fmaf(rv, s1.w, acc1[jj][7]);
                }
            }
        }

        // ---- KL for this 4x8 tile: two * log(two/one) ----
        #pragma unroll
        for (int jj = 0; jj < 4; ++jj)
            #pragma unroll
            for (int q = 0; q < 8; ++q) {
                float two = acc2[jj][q];
                float one = acc1[jj][q];
                kl = fmaf(two, acc_logf(__fdividef(two, one)), kl);
            }
    }

    // ---- deterministic block reduction ----
    #pragma unroll
    for (int o = 16; o > 0; o >>= 1)
        kl += __shfl_xor_sync(0xffffffffu, kl, o);

    __shared__ float sred[16];
    __shared__ bool  s_last;
    if ((tid & 31) == 0) sred[w] = kl;
    __syncthreads();

    if (tid == 0) {
        float s = 0.0f;
        #pragma unroll
        for (int x = 0; x < 16; ++x) s += sred[x];
        g_partial[b * 32 + i] = s;
        __threadfence();
        s_last = (atomicAdd(&g_count, 1) == 1023);
    }
    __syncthreads();

    // ---- last CTA: deterministic double-precision final reduce ----
    if (s_last && tid < 32) {
        __threadfence();
        double s = 0.0;
        #pragma unroll
        for (int it = 0; it < 32; ++it)
            s += (double)g_partial[it * 32 + tid];
        #pragma unroll
        for (int o = 16; o > 0; o >>= 1)
            s += __shfl_xor_sync(0xffffffffu, s, o);
        if (tid == 0) {
            out[0] = (float)(s * (1.0 / 32.0));   // / B
            g_count = 0;                          // reset for next graph replay
        }
    }
}

extern "C" void kernel_launch(void* const* d_in, const int* in_sizes, int n_in,
                              void* d_out, int out_size) {
    const float* A = (const float*)d_in[0];
    float* out = (float*)d_out;

    cudaFuncSetAttribute(assoc_kernel,
                         cudaFuncAttributeMaxDynamicSharedMemorySize, 135168);

    dim3 grid(32, 32);   // (i, b)
    assoc_kernel<<<grid, 512, 135168>>>(A, out);
}